// round 3
// baseline (speedup 1.0000x reference)
#include <cuda_runtime.h>
#include <cuda_fp16.h>
#include <math.h>

#define NNODES 50000
#define NEDGES 800000

// ---------------- scratch (static device globals; no allocation) ----------------
__device__ __align__(16) float g_x  [NNODES * 128];
__device__ __align__(16) float g_t1 [NNODES * 128];
__device__ __align__(16) float g_p  [NNODES * 128];
__device__ __align__(16) float g_h1 [NNODES * 128];
__device__ __align__(16) float g_tmp[NNODES * 128];
__device__ __align__(16) __half g_xh [NNODES * 128];
__device__ __align__(16) __half g_t1h[NNODES * 128];
__device__ __align__(16) __half g_h1h[NNODES * 128];
__device__ float g_dinv[NNODES];
__device__ int   g_deg [NNODES];
__device__ int   g_cnt [NNODES];
__device__ int   g_rs  [NNODES];
__device__ int   g_rf  [NNODES];
__device__ int   g_bsum[256];
__device__ __align__(8) int2 g_epack[NEDGES];   // (src, weight-bits) per CSR slot

// ---------------- CSR build ----------------
__global__ void count_kernel(const int* __restrict__ src, const int* __restrict__ dst,
                             int* __restrict__ deg, int* __restrict__ cnt, int E) {
    int e = blockIdx.x * blockDim.x + threadIdx.x;
    if (e < E) {
        atomicAdd(&deg[src[e]], 1);
        atomicAdd(&cnt[dst[e]], 1);
    }
}

// dinv from deg + per-block sums of cnt
__global__ void dinv_bsum_kernel(const int* __restrict__ deg, const int* __restrict__ cnt,
                                 float* __restrict__ dinv, int* __restrict__ bsum, int n) {
    __shared__ int wsum[8];
    int i = blockIdx.x * 256 + threadIdx.x;
    int lane = threadIdx.x & 31, wid = threadIdx.x >> 5;
    if (i < n) {
        int d = deg[i];
        dinv[i] = (d > 0) ? rsqrtf((float)d) : 0.f;
    }
    int v = (i < n) ? cnt[i] : 0;
#pragma unroll
    for (int o = 16; o > 0; o >>= 1) v += __shfl_down_sync(0xffffffffu, v, o);
    if (lane == 0) wsum[wid] = v;
    __syncthreads();
    if (threadIdx.x == 0) {
        int s = 0;
#pragma unroll
        for (int k = 0; k < 8; k++) s += wsum[k];
        bsum[blockIdx.x] = s;
    }
}

__device__ __forceinline__ int block_incl_scan(int v, int* wsum) {
    int lane = threadIdx.x & 31, wid = threadIdx.x >> 5;
    int x = v;
#pragma unroll
    for (int o = 1; o < 32; o <<= 1) {
        int y = __shfl_up_sync(0xffffffffu, x, o);
        if (lane >= o) x += y;
    }
    if (lane == 31) wsum[wid] = x;
    __syncthreads();
    if (wid == 0) {
        int s = (lane < 8) ? wsum[lane] : 0;
#pragma unroll
        for (int o = 1; o < 8; o <<= 1) {
            int y = __shfl_up_sync(0xffffffffu, s, o);
            if (lane >= o) s += y;
        }
        if (lane < 8) wsum[lane] = s;
    }
    __syncthreads();
    int off = (wid > 0) ? wsum[wid - 1] : 0;
    return x + off;
}

// exclusive scan with inline prefix over block sums
__global__ void scan_final(const int* __restrict__ cnt, const int* __restrict__ bsum,
                           int* __restrict__ rs, int* __restrict__ rf, int n) {
    __shared__ int wsum[8];
    __shared__ int boff_s;
    int i = blockIdx.x * 256 + threadIdx.x;
    int v = (i < n) ? cnt[i] : 0;
    int incl = block_incl_scan(v, wsum);
    if (threadIdx.x < 32) {
        int s = 0;
        for (int k = threadIdx.x; k < blockIdx.x; k += 32) s += bsum[k];
#pragma unroll
        for (int o = 16; o > 0; o >>= 1) s += __shfl_down_sync(0xffffffffu, s, o);
        if (threadIdx.x == 0) boff_s = s;
    }
    __syncthreads();
    int excl = incl - v + boff_s;
    if (i < n) { rs[i] = excl; rf[i] = excl; }
}

__global__ void fill_kernel(const int* __restrict__ src, const int* __restrict__ dst,
                            const float* __restrict__ dinv,
                            int* __restrict__ rf, int2* __restrict__ ep, int E) {
    int e = blockIdx.x * blockDim.x + threadIdx.x;
    if (e < E) {
        int s = src[e], d = dst[e];
        int pos = atomicAdd(&rf[d], 1);
        float w = -dinv[s] * dinv[d];
        ep[pos] = make_int2(s, __float_as_int(w));
    }
}

// ---------------- feature assembly: fp32 + fp16 shadow ----------------
__global__ void build_x_kernel(const int* __restrict__ node_attr,
                               const float4* __restrict__ vis,
                               const float4* __restrict__ emb_len,
                               const float4* __restrict__ emb_id,
                               const float4* __restrict__ emb_lng,
                               const float4* __restrict__ emb_lat,
                               float4* __restrict__ x, __half* __restrict__ xh, int n) {
    int idx = blockIdx.x * blockDim.x + threadIdx.x;
    if (idx >= n * 32) return;
    int node = idx >> 5;
    int q = idx & 31;
    float4 v;
    if (q < 16) {
        int which = q >> 2;
        int sub = q & 3;
        int a;
        const float4* tab;
        if (which == 0)      { a = node_attr[node * 4 + 1]; tab = emb_id; }
        else if (which == 1) { a = node_attr[node * 4 + 0]; tab = emb_len; }
        else if (which == 2) { a = node_attr[node * 4 + 2]; tab = emb_lng; }
        else                 { a = node_attr[node * 4 + 3]; tab = emb_lat; }
        v = tab[a * 4 + sub];
    } else {
        v = vis[node * 16 + (q - 16)];
    }
    x[idx] = v;
    __half2 h0 = __floats2half2_rn(v.x, v.y);
    __half2 h1 = __floats2half2_rn(v.z, v.w);
    uint2 u;
    u.x = *reinterpret_cast<unsigned*>(&h0);
    u.y = *reinterpret_cast<unsigned*>(&h1);
    *reinterpret_cast<uint2*>(xh + (size_t)idx * 4) = u;
}

// ---------------- gather propagation (fp16 operand, fp32 accumulate) ----------------
template<bool WH>
__global__ void prop_gather(const __half* __restrict__ t,
                            const int* __restrict__ rs, const int* __restrict__ cnt,
                            const int2* __restrict__ ep,
                            float* __restrict__ out, __half* __restrict__ outh, int n) {
    int warp = (blockIdx.x * blockDim.x + threadIdx.x) >> 5;
    int lane = threadIdx.x & 31;
    if (warp >= n) return;
    int start = rs[warp];
    int end = start + cnt[warp];
    const uint2* base = reinterpret_cast<const uint2*>(t);
    float a0 = 0.f, a1 = 0.f, a2 = 0.f, a3 = 0.f;
    int j = start;
    for (; j + 4 <= end; j += 4) {
        int2 m0 = ep[j], m1 = ep[j + 1], m2 = ep[j + 2], m3 = ep[j + 3];
        uint2 r0 = base[(size_t)m0.x * 32 + lane];
        uint2 r1 = base[(size_t)m1.x * 32 + lane];
        uint2 r2 = base[(size_t)m2.x * 32 + lane];
        uint2 r3 = base[(size_t)m3.x * 32 + lane];
        float w0 = __int_as_float(m0.y), w1 = __int_as_float(m1.y);
        float w2 = __int_as_float(m2.y), w3 = __int_as_float(m3.y);
        float2 f;
        f = __half22float2(*reinterpret_cast<__half2*>(&r0.x)); a0 += w0 * f.x; a1 += w0 * f.y;
        f = __half22float2(*reinterpret_cast<__half2*>(&r0.y)); a2 += w0 * f.x; a3 += w0 * f.y;
        f = __half22float2(*reinterpret_cast<__half2*>(&r1.x)); a0 += w1 * f.x; a1 += w1 * f.y;
        f = __half22float2(*reinterpret_cast<__half2*>(&r1.y)); a2 += w1 * f.x; a3 += w1 * f.y;
        f = __half22float2(*reinterpret_cast<__half2*>(&r2.x)); a0 += w2 * f.x; a1 += w2 * f.y;
        f = __half22float2(*reinterpret_cast<__half2*>(&r2.y)); a2 += w2 * f.x; a3 += w2 * f.y;
        f = __half22float2(*reinterpret_cast<__half2*>(&r3.x)); a0 += w3 * f.x; a1 += w3 * f.y;
        f = __half22float2(*reinterpret_cast<__half2*>(&r3.y)); a2 += w3 * f.x; a3 += w3 * f.y;
    }
    for (; j < end; j++) {
        int2 m = ep[j];
        uint2 r = base[(size_t)m.x * 32 + lane];
        float w = __int_as_float(m.y);
        float2 f;
        f = __half22float2(*reinterpret_cast<__half2*>(&r.x)); a0 += w * f.x; a1 += w * f.y;
        f = __half22float2(*reinterpret_cast<__half2*>(&r.y)); a2 += w * f.x; a3 += w * f.y;
    }
    *(float4*)(out + (size_t)warp * 128 + lane * 4) = make_float4(a0, a1, a2, a3);
    if (WH) {
        __half2 h0 = __floats2half2_rn(a0, a1);
        __half2 h1 = __floats2half2_rn(a2, a3);
        uint2 u;
        u.x = *reinterpret_cast<unsigned*>(&h0);
        u.y = *reinterpret_cast<unsigned*>(&h1);
        *reinterpret_cast<uint2*>(outh + (size_t)warp * 128 + lane * 4) = u;
    }
}

// ---------------- 3xTF32 tensor-core GEMM, packed (hi,lo) smem ----------------
__device__ __forceinline__ unsigned f2tf32(float f) {
    unsigned r;
    asm("cvt.rna.tf32.f32 %0, %1;" : "=r"(r) : "f"(f));
    return r;
}

__device__ __forceinline__ void mma_tf32(float& d0, float& d1, float& d2, float& d3,
                                         unsigned a0, unsigned a1, unsigned a2, unsigned a3,
                                         unsigned b0, unsigned b1) {
    asm volatile(
        "mma.sync.aligned.m16n8k8.row.col.f32.tf32.tf32.f32 "
        "{%0,%1,%2,%3}, {%4,%5,%6,%7}, {%8,%9}, {%0,%1,%2,%3};"
        : "+f"(d0), "+f"(d1), "+f"(d2), "+f"(d3)
        : "r"(a0), "r"(a1), "r"(a2), "r"(a3), "r"(b0), "r"(b1));
}

__device__ __forceinline__ uint2 split_tf32(float f) {
    unsigned hi = f2tf32(f);
    unsigned lo = f2tf32(f - __uint_as_float(hi));
    return make_uint2(hi, lo);
}

// C[M,NOUT] = A[M,KTOT] @ W[KTOT,NOUT] + bias; EPI: 0=none 1=relu 2=elu
// CHEB: A cols 0..127 = A0, 128..255 = A1, 256..383 = 2*A2 - A0
// WH: also write fp16 shadow of C to Ch
template<int KTOT, int NOUT, int EPI, bool CHEB, bool WH>
__global__ void __launch_bounds__(256)
gemm_tf32(const float* __restrict__ A0, const float* __restrict__ A1,
          const float* __restrict__ A2, const float* __restrict__ W,
          const float* __restrict__ bias, float* __restrict__ C,
          __half* __restrict__ Ch, int M) {
    constexpr int BM = 128, BK = 16, BN = NOUT;
    constexpr int WARP_N = BN / 2;
    constexpr int NT = WARP_N / 8;

    __shared__ uint2 As[BK][BM + 4];   // (hi,lo)
    __shared__ uint2 Bs[BK][BN + 4];

    const int tid = threadIdx.x;
    const int w = tid >> 5, lane = tid & 31;
    const int wm = w & 3, wn = w >> 2;
    const int gid = lane >> 2, tig = lane & 3;
    const int row0 = blockIdx.x * BM;

    float acc[2][NT][4];
#pragma unroll
    for (int mt = 0; mt < 2; mt++)
#pragma unroll
        for (int nt = 0; nt < NT; nt++)
#pragma unroll
            for (int q = 0; q < 4; q++) acc[mt][nt][q] = 0.f;

    for (int k0 = 0; k0 < KTOT; k0 += BK) {
        // ---- stage A ----
#pragma unroll
        for (int it = 0; it < 2; it++) {
            int i = tid + it * 256;        // 0..511
            int r = i & 127;
            int c4 = i >> 7;               // 0..3
            int grow = row0 + r;
            int gk = k0 + c4 * 4;
            float4 v = make_float4(0.f, 0.f, 0.f, 0.f);
            if (grow < M) {
                if (CHEB) {
                    if (gk < 128) {
                        v = *(const float4*)(A0 + (size_t)grow * 128 + gk);
                    } else if (gk < 256) {
                        v = *(const float4*)(A1 + (size_t)grow * 128 + (gk - 128));
                    } else {
                        float4 p = *(const float4*)(A2 + (size_t)grow * 128 + (gk - 256));
                        float4 t = *(const float4*)(A0 + (size_t)grow * 128 + (gk - 256));
                        v = make_float4(2.f * p.x - t.x, 2.f * p.y - t.y,
                                        2.f * p.z - t.z, 2.f * p.w - t.w);
                    }
                } else {
                    v = *(const float4*)(A0 + (size_t)grow * KTOT + gk);
                }
            }
            float fv[4] = {v.x, v.y, v.z, v.w};
#pragma unroll
            for (int j = 0; j < 4; j++)
                As[c4 * 4 + j][r] = split_tf32(fv[j]);
        }
        // ---- stage B: strided columns, conflict-free STS ----
        constexpr int TPR = BN / 4;                 // threads per k-row
        constexpr int ROWS_PER_PASS = 256 / TPR;
#pragma unroll
        for (int it = 0; it < BK / ROWS_PER_PASS; it++) {
            int kk = (tid / TPR) + it * ROWS_PER_PASS;
            int c0 = tid % TPR;
#pragma unroll
            for (int q = 0; q < 4; q++) {
                int c = c0 + q * TPR;
                float fv = W[(size_t)(k0 + kk) * BN + c];
                Bs[kk][c] = split_tf32(fv);
            }
        }
        __syncthreads();

#pragma unroll
        for (int ks = 0; ks < 2; ks++) {
            const int kr = ks * 8 + tig;
            unsigned ah[2][4], al[2][4];
#pragma unroll
            for (int mt = 0; mt < 2; mt++) {
                int m0 = wm * 32 + mt * 16 + gid;
                uint2 q0 = As[kr][m0];
                uint2 q1 = As[kr][m0 + 8];
                uint2 q2 = As[kr + 4][m0];
                uint2 q3 = As[kr + 4][m0 + 8];
                ah[mt][0] = q0.x; ah[mt][1] = q1.x; ah[mt][2] = q2.x; ah[mt][3] = q3.x;
                al[mt][0] = q0.y; al[mt][1] = q1.y; al[mt][2] = q2.y; al[mt][3] = q3.y;
            }
            unsigned bh[NT][2], bl[NT][2];
#pragma unroll
            for (int nt = 0; nt < NT; nt++) {
                int n0 = wn * WARP_N + nt * 8 + gid;
                uint2 r0 = Bs[kr][n0];
                uint2 r1 = Bs[kr + 4][n0];
                bh[nt][0] = r0.x; bh[nt][1] = r1.x;
                bl[nt][0] = r0.y; bl[nt][1] = r1.y;
            }
#pragma unroll
            for (int mt = 0; mt < 2; mt++)
#pragma unroll
                for (int nt = 0; nt < NT; nt++) {
                    float* d = acc[mt][nt];
                    mma_tf32(d[0], d[1], d[2], d[3],
                             ah[mt][0], ah[mt][1], ah[mt][2], ah[mt][3],
                             bh[nt][0], bh[nt][1]);
                    mma_tf32(d[0], d[1], d[2], d[3],
                             ah[mt][0], ah[mt][1], ah[mt][2], ah[mt][3],
                             bl[nt][0], bl[nt][1]);
                    mma_tf32(d[0], d[1], d[2], d[3],
                             al[mt][0], al[mt][1], al[mt][2], al[mt][3],
                             bh[nt][0], bh[nt][1]);
                }
        }
        __syncthreads();
    }

    // ---- epilogue ----
#pragma unroll
    for (int mt = 0; mt < 2; mt++) {
#pragma unroll
        for (int nt = 0; nt < NT; nt++) {
            int c0 = wn * WARP_N + nt * 8 + tig * 2;
            float bv0 = bias[c0], bv1 = bias[c0 + 1];
#pragma unroll
            for (int half = 0; half < 2; half++) {
                int r = row0 + wm * 32 + mt * 16 + gid + half * 8;
                if (r >= M) continue;
                float v0 = acc[mt][nt][half * 2 + 0] + bv0;
                float v1 = acc[mt][nt][half * 2 + 1] + bv1;
                if (EPI == 1) { v0 = fmaxf(v0, 0.f); v1 = fmaxf(v1, 0.f); }
                else if (EPI == 2) {
                    v0 = (v0 > 0.f) ? v0 : expm1f(v0);
                    v1 = (v1 > 0.f) ? v1 : expm1f(v1);
                }
                *(float2*)(C + (size_t)r * NOUT + c0) = make_float2(v0, v1);
                if (WH) {
                    __half2 h = __floats2half2_rn(v0, v1);
                    *reinterpret_cast<__half2*>(Ch + (size_t)r * NOUT + c0) = h;
                }
            }
        }
    }
}

// ---------------- launch ----------------
extern "C" void kernel_launch(void* const* d_in, const int* in_sizes, int n_in,
                              void* d_out, int out_size) {
    const int* edge_index = (const int*)d_in[0];
    const int* node_attr = (const int*)d_in[1];
    const float* vis     = (const float*)d_in[2];
    const float* emb_len = (const float*)d_in[3];
    const float* emb_id  = (const float*)d_in[4];
    const float* emb_lng = (const float*)d_in[5];
    const float* emb_lat = (const float*)d_in[6];
    const float* W0  = (const float*)d_in[7];
    const float* b0  = (const float*)d_in[8];
    const float* W1  = (const float*)d_in[9];
    const float* b1  = (const float*)d_in[10];
    const float* P1  = (const float*)d_in[11];
    const float* pb1 = (const float*)d_in[12];
    const float* P2  = (const float*)d_in[13];
    const float* pb2 = (const float*)d_in[14];

    const int E = in_sizes[0] / 2;
    const int N = in_sizes[1] / 4;
    const int* src = edge_index;
    const int* dst = edge_index + E;

    float *x, *t1, *p, *h1, *tmp, *dinv;
    __half *xh, *t1h, *h1h;
    int *deg, *cnt, *rs, *rf, *bsum;
    int2* ep;
    cudaGetSymbolAddress((void**)&x,    g_x);
    cudaGetSymbolAddress((void**)&t1,   g_t1);
    cudaGetSymbolAddress((void**)&p,    g_p);
    cudaGetSymbolAddress((void**)&h1,   g_h1);
    cudaGetSymbolAddress((void**)&tmp,  g_tmp);
    cudaGetSymbolAddress((void**)&xh,   g_xh);
    cudaGetSymbolAddress((void**)&t1h,  g_t1h);
    cudaGetSymbolAddress((void**)&h1h,  g_h1h);
    cudaGetSymbolAddress((void**)&dinv, g_dinv);
    cudaGetSymbolAddress((void**)&deg,  g_deg);
    cudaGetSymbolAddress((void**)&cnt,  g_cnt);
    cudaGetSymbolAddress((void**)&rs,   g_rs);
    cudaGetSymbolAddress((void**)&rf,   g_rf);
    cudaGetSymbolAddress((void**)&bsum, g_bsum);
    cudaGetSymbolAddress((void**)&ep,   g_epack);

    float* hout = (float*)d_out;
    float* zout = hout + (size_t)N * 128;

    const int nb = (N + 255) / 256;
    const int eb = (E + 255) / 256;
    const int gemm_blocks = (N + 127) / 128;
    const int prop_blocks = (N * 32 + 255) / 256;

    // CSR build + dinv (zero via memset nodes, not kernels)
    cudaMemsetAsync(deg, 0, N * sizeof(int));
    cudaMemsetAsync(cnt, 0, N * sizeof(int));
    count_kernel<<<eb, 256>>>(src, dst, deg, cnt, E);
    dinv_bsum_kernel<<<nb, 256>>>(deg, cnt, dinv, bsum, N);
    scan_final<<<nb, 256>>>(cnt, bsum, rs, rf, N);
    fill_kernel<<<eb, 256>>>(src, dst, dinv, rf, ep, E);

    // feature assembly
    build_x_kernel<<<(N * 32 + 255) / 256, 256>>>(node_attr, (const float4*)vis,
        (const float4*)emb_len, (const float4*)emb_id,
        (const float4*)emb_lng, (const float4*)emb_lat, (float4*)x, xh, N);

    // ---- conv1 ----
    prop_gather<true ><<<prop_blocks, 256>>>(xh,  rs, cnt, ep, t1, t1h, N);
    prop_gather<false><<<prop_blocks, 256>>>(t1h, rs, cnt, ep, p,  nullptr, N);
    gemm_tf32<384, 128, 1, true, true><<<gemm_blocks, 256>>>(x, t1, p, W0, b0, h1, h1h, N);

    // ---- conv2 ----
    prop_gather<true ><<<prop_blocks, 256>>>(h1h, rs, cnt, ep, t1, t1h, N);
    prop_gather<false><<<prop_blocks, 256>>>(t1h, rs, cnt, ep, p,  nullptr, N);
    gemm_tf32<384, 128, 1, true, false><<<gemm_blocks, 256>>>(h1, t1, p, W1, b1, hout, nullptr, N);

    // ---- projection head ----
    gemm_tf32<128, 128, 2, false, false><<<gemm_blocks, 256>>>(hout, nullptr, nullptr, P1, pb1, tmp, nullptr, N);
    gemm_tf32<128, 64, 0, false, false><<<gemm_blocks, 256>>>(tmp, nullptr, nullptr, P2, pb2, zout, nullptr, N);
}

// round 4
// speedup vs baseline: 1.1597x; 1.1597x over previous
#include <cuda_runtime.h>
#include <math.h>

#define NNODES 50000
#define NEDGES 800000

// ---------------- scratch (static device globals; no allocation) ----------------
__device__ __align__(16) float g_x  [NNODES * 128];
__device__ __align__(16) float g_t1 [NNODES * 128];
__device__ __align__(16) float g_p  [NNODES * 128];
__device__ __align__(16) float g_h1 [NNODES * 128];
__device__ __align__(16) float g_tmp[NNODES * 128];
__device__ int   g_deg [NNODES];
__device__ int   g_cnt [NNODES];
__device__ int   g_rs  [NNODES];
__device__ int   g_rf  [NNODES];
__device__ int   g_bsum[256];
__device__ __align__(8) int2 g_epack[NEDGES];   // (src, weight-bits) per CSR slot

// ---------------- feature assembly + zero counters (launch #1) ----------------
__global__ void build_x_kernel(const int* __restrict__ node_attr,
                               const float4* __restrict__ vis,
                               const float4* __restrict__ emb_len,
                               const float4* __restrict__ emb_id,
                               const float4* __restrict__ emb_lng,
                               const float4* __restrict__ emb_lat,
                               float4* __restrict__ x,
                               int* __restrict__ deg, int* __restrict__ cnt, int n) {
    int idx = blockIdx.x * blockDim.x + threadIdx.x;
    if (idx < n) { deg[idx] = 0; cnt[idx] = 0; }
    if (idx >= n * 32) return;
    int node = idx >> 5;
    int q = idx & 31;
    float4 v;
    if (q < 16) {
        int which = q >> 2;  // 0:id 1:len 2:lng 3:lat
        int sub = q & 3;
        int a;
        const float4* tab;
        if (which == 0)      { a = node_attr[node * 4 + 1]; tab = emb_id; }
        else if (which == 1) { a = node_attr[node * 4 + 0]; tab = emb_len; }
        else if (which == 2) { a = node_attr[node * 4 + 2]; tab = emb_lng; }
        else                 { a = node_attr[node * 4 + 3]; tab = emb_lat; }
        v = tab[a * 4 + sub];
    } else {
        v = vis[node * 16 + (q - 16)];
    }
    x[idx] = v;
}

// ---------------- CSR build ----------------
__global__ void count_kernel(const int* __restrict__ src, const int* __restrict__ dst,
                             int* __restrict__ deg, int* __restrict__ cnt, int E) {
    int e = blockIdx.x * blockDim.x + threadIdx.x;
    if (e < E) {
        atomicAdd(&deg[src[e]], 1);
        atomicAdd(&cnt[dst[e]], 1);
    }
}

__global__ void scan_block_sum(const int* __restrict__ cnt, int* __restrict__ bsum, int n) {
    __shared__ int wsum[8];
    int i = blockIdx.x * 256 + threadIdx.x;
    int v = (i < n) ? cnt[i] : 0;
    int lane = threadIdx.x & 31, wid = threadIdx.x >> 5;
#pragma unroll
    for (int o = 16; o > 0; o >>= 1) v += __shfl_down_sync(0xffffffffu, v, o);
    if (lane == 0) wsum[wid] = v;
    __syncthreads();
    if (threadIdx.x == 0) {
        int s = 0;
#pragma unroll
        for (int k = 0; k < 8; k++) s += wsum[k];
        bsum[blockIdx.x] = s;
    }
}

__device__ __forceinline__ int block_incl_scan(int v, int* wsum) {
    int lane = threadIdx.x & 31, wid = threadIdx.x >> 5;
    int x = v;
#pragma unroll
    for (int o = 1; o < 32; o <<= 1) {
        int y = __shfl_up_sync(0xffffffffu, x, o);
        if (lane >= o) x += y;
    }
    if (lane == 31) wsum[wid] = x;
    __syncthreads();
    if (wid == 0) {
        int s = (lane < 8) ? wsum[lane] : 0;
#pragma unroll
        for (int o = 1; o < 8; o <<= 1) {
            int y = __shfl_up_sync(0xffffffffu, s, o);
            if (lane >= o) s += y;
        }
        if (lane < 8) wsum[lane] = s;
    }
    __syncthreads();
    int off = (wid > 0) ? wsum[wid - 1] : 0;
    return x + off;
}

// exclusive scan with inline prefix over block sums
__global__ void scan_final(const int* __restrict__ cnt, const int* __restrict__ bsum,
                           int* __restrict__ rs, int* __restrict__ rf, int n) {
    __shared__ int wsum[8];
    __shared__ int boff_s;
    int i = blockIdx.x * 256 + threadIdx.x;
    int v = (i < n) ? cnt[i] : 0;
    int incl = block_incl_scan(v, wsum);
    if (threadIdx.x < 32) {
        int s = 0;
        for (int k = threadIdx.x; k < blockIdx.x; k += 32) s += bsum[k];
#pragma unroll
        for (int o = 16; o > 0; o >>= 1) s += __shfl_down_sync(0xffffffffu, s, o);
        if (threadIdx.x == 0) boff_s = s;
    }
    __syncthreads();
    int excl = incl - v + boff_s;
    if (i < n) { rs[i] = excl; rf[i] = excl; }
}

// fill CSR slots; weight computed directly from degree counts
__global__ void fill_kernel(const int* __restrict__ src, const int* __restrict__ dst,
                            const int* __restrict__ deg,
                            int* __restrict__ rf, int2* __restrict__ ep, int E) {
    int e = blockIdx.x * blockDim.x + threadIdx.x;
    if (e < E) {
        int s = src[e], d = dst[e];
        int pos = atomicAdd(&rf[d], 1);
        int ds = deg[s], dd = deg[d];
        float w = (dd > 0) ? -rsqrtf((float)ds * (float)dd) : 0.f;
        ep[pos] = make_int2(s, __float_as_int(w));
    }
}

// ---------------- gather propagation (fp32, shuffle-broadcast metadata) ----------------
__global__ void prop_gather(const float* __restrict__ t,
                            const int* __restrict__ rs, const int* __restrict__ cnt,
                            const int2* __restrict__ ep,
                            float* __restrict__ out, int n) {
    int warp = (blockIdx.x * blockDim.x + threadIdx.x) >> 5;
    int lane = threadIdx.x & 31;
    if (warp >= n) return;
    int start = rs[warp];
    int m = cnt[warp];
    float a0 = 0.f, a1 = 0.f, a2 = 0.f, a3 = 0.f;
    for (int j0 = 0; j0 < m; j0 += 8) {
        int nb = m - j0; if (nb > 8) nb = 8;
        int2 md = make_int2(0, 0);
        if (lane < nb) md = ep[start + j0 + lane];
#pragma unroll
        for (int k = 0; k < 8; k++) {
            if (k >= nb) break;
            int s = __shfl_sync(0xffffffffu, md.x, k);
            float w = __int_as_float(__shfl_sync(0xffffffffu, md.y, k));
            float4 v = *(const float4*)(t + (size_t)s * 128 + lane * 4);
            a0 += w * v.x; a1 += w * v.y; a2 += w * v.z; a3 += w * v.w;
        }
    }
    *(float4*)(out + (size_t)warp * 128 + lane * 4) = make_float4(a0, a1, a2, a3);
}

// ---------------- 3xTF32 tensor-core GEMM (round-2 proven version) ----------------
__device__ __forceinline__ unsigned f2tf32(float f) {
    unsigned r;
    asm("cvt.rna.tf32.f32 %0, %1;" : "=r"(r) : "f"(f));
    return r;
}

__device__ __forceinline__ void mma_tf32(float& d0, float& d1, float& d2, float& d3,
                                         unsigned a0, unsigned a1, unsigned a2, unsigned a3,
                                         unsigned b0, unsigned b1) {
    asm volatile(
        "mma.sync.aligned.m16n8k8.row.col.f32.tf32.tf32.f32 "
        "{%0,%1,%2,%3}, {%4,%5,%6,%7}, {%8,%9}, {%0,%1,%2,%3};"
        : "+f"(d0), "+f"(d1), "+f"(d2), "+f"(d3)
        : "r"(a0), "r"(a1), "r"(a2), "r"(a3), "r"(b0), "r"(b1));
}

template<int KTOT, int NOUT, int EPI, bool CHEB>
__global__ void __launch_bounds__(256)
gemm_tf32(const float* __restrict__ A0, const float* __restrict__ A1,
          const float* __restrict__ A2, const float* __restrict__ W,
          const float* __restrict__ bias, float* __restrict__ C, int M) {
    constexpr int BM = 128, BK = 16, BN = NOUT;
    constexpr int WARP_N = BN / 2;
    constexpr int NT = WARP_N / 8;

    __shared__ unsigned Ah[BK][BM + 8], Al[BK][BM + 8];
    __shared__ unsigned Bh[BK][BN + 8], Bl[BK][BN + 8];

    const int tid = threadIdx.x;
    const int w = tid >> 5, lane = tid & 31;
    const int wm = w & 3, wn = w >> 2;
    const int gid = lane >> 2, tig = lane & 3;
    const int row0 = blockIdx.x * BM;

    float acc[2][NT][4];
#pragma unroll
    for (int mt = 0; mt < 2; mt++)
#pragma unroll
        for (int nt = 0; nt < NT; nt++)
#pragma unroll
            for (int q = 0; q < 4; q++) acc[mt][nt][q] = 0.f;

    for (int k0 = 0; k0 < KTOT; k0 += BK) {
        // ---- stage A ----
#pragma unroll
        for (int it = 0; it < 2; it++) {
            int i = tid + it * 256;
            int r = i & 127;
            int c4 = i >> 7;
            int grow = row0 + r;
            int gk = k0 + c4 * 4;
            float4 v = make_float4(0.f, 0.f, 0.f, 0.f);
            if (grow < M) {
                if (CHEB) {
                    if (gk < 128) {
                        v = *(const float4*)(A0 + (size_t)grow * 128 + gk);
                    } else if (gk < 256) {
                        v = *(const float4*)(A1 + (size_t)grow * 128 + (gk - 128));
                    } else {
                        float4 p = *(const float4*)(A2 + (size_t)grow * 128 + (gk - 256));
                        float4 t = *(const float4*)(A0 + (size_t)grow * 128 + (gk - 256));
                        v = make_float4(2.f * p.x - t.x, 2.f * p.y - t.y,
                                        2.f * p.z - t.z, 2.f * p.w - t.w);
                    }
                } else {
                    v = *(const float4*)(A0 + (size_t)grow * KTOT + gk);
                }
            }
            float fv[4] = {v.x, v.y, v.z, v.w};
#pragma unroll
            for (int j = 0; j < 4; j++) {
                unsigned hi = f2tf32(fv[j]);
                unsigned lo = f2tf32(fv[j] - __uint_as_float(hi));
                Ah[c4 * 4 + j][r] = hi;
                Al[c4 * 4 + j][r] = lo;
            }
        }
        // ---- stage B (W) ----
#pragma unroll
        for (int it = 0; it < BN / 64; it++) {
            int i = tid + it * 256;
            int kk = i / (BN / 4);
            int c = (i % (BN / 4)) * 4;
            float4 v = *(const float4*)(W + (size_t)(k0 + kk) * BN + c);
            float fv[4] = {v.x, v.y, v.z, v.w};
            unsigned h4[4], l4[4];
#pragma unroll
            for (int j = 0; j < 4; j++) {
                h4[j] = f2tf32(fv[j]);
                l4[j] = f2tf32(fv[j] - __uint_as_float(h4[j]));
            }
            *(uint4*)&Bh[kk][c] = make_uint4(h4[0], h4[1], h4[2], h4[3]);
            *(uint4*)&Bl[kk][c] = make_uint4(l4[0], l4[1], l4[2], l4[3]);
        }
        __syncthreads();

#pragma unroll
        for (int ks = 0; ks < 2; ks++) {
            const int kr = ks * 8 + tig;
            unsigned ah[2][4], al[2][4];
#pragma unroll
            for (int mt = 0; mt < 2; mt++) {
                int m0 = wm * 32 + mt * 16 + gid;
                ah[mt][0] = Ah[kr][m0];     ah[mt][1] = Ah[kr][m0 + 8];
                ah[mt][2] = Ah[kr + 4][m0]; ah[mt][3] = Ah[kr + 4][m0 + 8];
                al[mt][0] = Al[kr][m0];     al[mt][1] = Al[kr][m0 + 8];
                al[mt][2] = Al[kr + 4][m0]; al[mt][3] = Al[kr + 4][m0 + 8];
            }
            unsigned bh[NT][2], bl[NT][2];
#pragma unroll
            for (int nt = 0; nt < NT; nt++) {
                int n0 = wn * WARP_N + nt * 8 + gid;
                bh[nt][0] = Bh[kr][n0]; bh[nt][1] = Bh[kr + 4][n0];
                bl[nt][0] = Bl[kr][n0]; bl[nt][1] = Bl[kr + 4][n0];
            }
#pragma unroll
            for (int mt = 0; mt < 2; mt++)
#pragma unroll
                for (int nt = 0; nt < NT; nt++) {
                    float* d = acc[mt][nt];
                    mma_tf32(d[0], d[1], d[2], d[3],
                             ah[mt][0], ah[mt][1], ah[mt][2], ah[mt][3],
                             bh[nt][0], bh[nt][1]);
                    mma_tf32(d[0], d[1], d[2], d[3],
                             ah[mt][0], ah[mt][1], ah[mt][2], ah[mt][3],
                             bl[nt][0], bl[nt][1]);
                    mma_tf32(d[0], d[1], d[2], d[3],
                             al[mt][0], al[mt][1], al[mt][2], al[mt][3],
                             bh[nt][0], bh[nt][1]);
                }
        }
        __syncthreads();
    }

    // ---- epilogue ----
#pragma unroll
    for (int mt = 0; mt < 2; mt++) {
#pragma unroll
        for (int nt = 0; nt < NT; nt++) {
            int c0 = wn * WARP_N + nt * 8 + tig * 2;
            float bv0 = bias[c0], bv1 = bias[c0 + 1];
#pragma unroll
            for (int half = 0; half < 2; half++) {
                int r = row0 + wm * 32 + mt * 16 + gid + half * 8;
                if (r >= M) continue;
                float v0 = acc[mt][nt][half * 2 + 0] + bv0;
                float v1 = acc[mt][nt][half * 2 + 1] + bv1;
                if (EPI == 1) { v0 = fmaxf(v0, 0.f); v1 = fmaxf(v1, 0.f); }
                else if (EPI == 2) {
                    v0 = (v0 > 0.f) ? v0 : expm1f(v0);
                    v1 = (v1 > 0.f) ? v1 : expm1f(v1);
                }
                *(float2*)(C + (size_t)r * NOUT + c0) = make_float2(v0, v1);
            }
        }
    }
}

// ---------------- launch ----------------
extern "C" void kernel_launch(void* const* d_in, const int* in_sizes, int n_in,
                              void* d_out, int out_size) {
    const int* edge_index = (const int*)d_in[0];
    const int* node_attr = (const int*)d_in[1];
    const float* vis     = (const float*)d_in[2];
    const float* emb_len = (const float*)d_in[3];
    const float* emb_id  = (const float*)d_in[4];
    const float* emb_lng = (const float*)d_in[5];
    const float* emb_lat = (const float*)d_in[6];
    const float* W0  = (const float*)d_in[7];
    const float* b0  = (const float*)d_in[8];
    const float* W1  = (const float*)d_in[9];
    const float* b1  = (const float*)d_in[10];
    const float* P1  = (const float*)d_in[11];
    const float* pb1 = (const float*)d_in[12];
    const float* P2  = (const float*)d_in[13];
    const float* pb2 = (const float*)d_in[14];

    const int E = in_sizes[0] / 2;
    const int N = in_sizes[1] / 4;
    const int* src = edge_index;
    const int* dst = edge_index + E;

    float *x, *t1, *p, *h1, *tmp;
    int *deg, *cnt, *rs, *rf, *bsum;
    int2* ep;
    cudaGetSymbolAddress((void**)&x,    g_x);
    cudaGetSymbolAddress((void**)&t1,   g_t1);
    cudaGetSymbolAddress((void**)&p,    g_p);
    cudaGetSymbolAddress((void**)&h1,   g_h1);
    cudaGetSymbolAddress((void**)&tmp,  g_tmp);
    cudaGetSymbolAddress((void**)&deg,  g_deg);
    cudaGetSymbolAddress((void**)&cnt,  g_cnt);
    cudaGetSymbolAddress((void**)&rs,   g_rs);
    cudaGetSymbolAddress((void**)&rf,   g_rf);
    cudaGetSymbolAddress((void**)&bsum, g_bsum);
    cudaGetSymbolAddress((void**)&ep,   g_epack);

    float* hout = (float*)d_out;
    float* zout = hout + (size_t)N * 128;

    const int nb = (N + 255) / 256;
    const int eb = (E + 255) / 256;
    const int gemm_blocks = (N + 127) / 128;
    const int prop_blocks = (N * 32 + 255) / 256;

    // setup: exactly 5 launches so -s 5 -c 1 profiles prop #1
    build_x_kernel<<<(N * 32 + 255) / 256, 256>>>(node_attr, (const float4*)vis,
        (const float4*)emb_len, (const float4*)emb_id,
        (const float4*)emb_lng, (const float4*)emb_lat, (float4*)x, deg, cnt, N);
    count_kernel<<<eb, 256>>>(src, dst, deg, cnt, E);
    scan_block_sum<<<nb, 256>>>(cnt, bsum, N);
    scan_final<<<nb, 256>>>(cnt, bsum, rs, rf, N);
    fill_kernel<<<eb, 256>>>(src, dst, deg, rf, ep, E);

    // ---- conv1 ----
    prop_gather<<<prop_blocks, 256>>>(x, rs, cnt, ep, t1, N);
    prop_gather<<<prop_blocks, 256>>>(t1, rs, cnt, ep, p, N);
    gemm_tf32<384, 128, 1, true><<<gemm_blocks, 256>>>(x, t1, p, W0, b0, h1, N);

    // ---- conv2 ----
    prop_gather<<<prop_blocks, 256>>>(h1, rs, cnt, ep, t1, N);
    prop_gather<<<prop_blocks, 256>>>(t1, rs, cnt, ep, p, N);
    gemm_tf32<384, 128, 1, true><<<gemm_blocks, 256>>>(h1, t1, p, W1, b1, hout, N);

    // ---- projection head ----
    gemm_tf32<128, 128, 2, false><<<gemm_blocks, 256>>>(hout, nullptr, nullptr, P1, pb1, tmp, N);
    gemm_tf32<128, 64, 0, false><<<gemm_blocks, 256>>>(tmp, nullptr, nullptr, P2, pb2, zout, N);
}

// round 6
// speedup vs baseline: 1.5564x; 1.3421x over previous
#include <cuda_runtime.h>
#include <cuda_fp16.h>
#include <math.h>

#define NNODES 50000
#define NEDGES 800000

// ---------------- scratch (static device globals; no allocation) ----------------
__device__ __align__(16) float g_x  [NNODES * 128];
__device__ __align__(16) float g_t1 [NNODES * 128];
__device__ __align__(16) float g_p  [NNODES * 128];
__device__ __align__(16) float g_h1 [NNODES * 128];
__device__ __align__(16) float g_tmp[NNODES * 128];
__device__ float g_dinv[NNODES];
__device__ int   g_deg [NNODES];
__device__ int   g_cnt [NNODES];
__device__ int   g_rs  [NNODES];
__device__ int   g_rf  [NNODES];
__device__ int   g_bsum[256];
__device__ int   g_boff[256];
__device__ int   g_esrc[NEDGES];
__device__ float g_ew  [NEDGES];

// ---------------- CSR build (round-2 proven) ----------------
__global__ void count_kernel(const int* __restrict__ src, const int* __restrict__ dst,
                             int* __restrict__ deg, int* __restrict__ cnt, int E) {
    int e = blockIdx.x * blockDim.x + threadIdx.x;
    if (e < E) {
        atomicAdd(&deg[src[e]], 1);
        atomicAdd(&cnt[dst[e]], 1);
    }
}

__global__ void dinv_kernel(const int* __restrict__ deg, float* __restrict__ dinv, int n) {
    int i = blockIdx.x * blockDim.x + threadIdx.x;
    if (i < n) {
        int d = deg[i];
        dinv[i] = (d > 0) ? rsqrtf((float)d) : 0.f;
    }
}

__device__ __forceinline__ int block_incl_scan(int v, int* wsum) {
    int lane = threadIdx.x & 31, wid = threadIdx.x >> 5;
    int x = v;
#pragma unroll
    for (int o = 1; o < 32; o <<= 1) {
        int y = __shfl_up_sync(0xffffffffu, x, o);
        if (lane >= o) x += y;
    }
    if (lane == 31) wsum[wid] = x;
    __syncthreads();
    if (wid == 0) {
        int s = (lane < 8) ? wsum[lane] : 0;
#pragma unroll
        for (int o = 1; o < 8; o <<= 1) {
            int y = __shfl_up_sync(0xffffffffu, s, o);
            if (lane >= o) s += y;
        }
        if (lane < 8) wsum[lane] = s;
    }
    __syncthreads();
    int off = (wid > 0) ? wsum[wid - 1] : 0;
    return x + off;
}

__global__ void scan_block_sum(const int* __restrict__ cnt, int* __restrict__ bsum, int n) {
    __shared__ int wsum[8];
    int i = blockIdx.x * 256 + threadIdx.x;
    int v = (i < n) ? cnt[i] : 0;
    int lane = threadIdx.x & 31, wid = threadIdx.x >> 5;
#pragma unroll
    for (int o = 16; o > 0; o >>= 1) v += __shfl_down_sync(0xffffffffu, v, o);
    if (lane == 0) wsum[wid] = v;
    __syncthreads();
    if (threadIdx.x == 0) {
        int s = 0;
#pragma unroll
        for (int k = 0; k < 8; k++) s += wsum[k];
        bsum[blockIdx.x] = s;
    }
}

__global__ void scan_top(const int* __restrict__ bsum, int* __restrict__ boff, int nb) {
    __shared__ int wsum[8];
    int t = threadIdx.x;
    int v = (t < nb) ? bsum[t] : 0;
    int incl = block_incl_scan(v, wsum);
    if (t < nb) boff[t] = incl - v;
}

__global__ void scan_final(const int* __restrict__ cnt, const int* __restrict__ boff,
                           int* __restrict__ rs, int* __restrict__ rf, int n) {
    __shared__ int wsum[8];
    int i = blockIdx.x * 256 + threadIdx.x;
    int v = (i < n) ? cnt[i] : 0;
    int incl = block_incl_scan(v, wsum);
    int excl = incl - v + boff[blockIdx.x];
    if (i < n) { rs[i] = excl; rf[i] = excl; }
}

__global__ void fill_kernel(const int* __restrict__ src, const int* __restrict__ dst,
                            const float* __restrict__ dinv,
                            int* __restrict__ rf, int* __restrict__ esrc,
                            float* __restrict__ ew, int E) {
    int e = blockIdx.x * blockDim.x + threadIdx.x;
    if (e < E) {
        int s = src[e], d = dst[e];
        int pos = atomicAdd(&rf[d], 1);
        esrc[pos] = s;
        ew[pos] = -dinv[s] * dinv[d];
    }
}

// ---------------- feature assembly (float4) ----------------
__global__ void build_x_kernel(const int* __restrict__ node_attr,
                               const float4* __restrict__ vis,
                               const float4* __restrict__ emb_len,
                               const float4* __restrict__ emb_id,
                               const float4* __restrict__ emb_lng,
                               const float4* __restrict__ emb_lat,
                               float4* __restrict__ x, int n) {
    int idx = blockIdx.x * blockDim.x + threadIdx.x;
    if (idx >= n * 32) return;
    int node = idx >> 5;
    int q = idx & 31;
    float4 v;
    if (q < 16) {
        int which = q >> 2;
        int sub = q & 3;
        int a;
        const float4* tab;
        if (which == 0)      { a = node_attr[node * 4 + 1]; tab = emb_id; }
        else if (which == 1) { a = node_attr[node * 4 + 0]; tab = emb_len; }
        else if (which == 2) { a = node_attr[node * 4 + 2]; tab = emb_lng; }
        else                 { a = node_attr[node * 4 + 3]; tab = emb_lat; }
        v = tab[a * 4 + sub];
    } else {
        v = vis[node * 16 + (q - 16)];
    }
    x[idx] = v;
}

// ---------------- gather propagation (round-2 proven) ----------------
__global__ void prop_gather(const float* __restrict__ t,
                            const int* __restrict__ rs, const int* __restrict__ cnt,
                            const int* __restrict__ esrc, const float* __restrict__ ew,
                            float* __restrict__ out, int n) {
    int warp = (blockIdx.x * blockDim.x + threadIdx.x) >> 5;
    int lane = threadIdx.x & 31;
    if (warp >= n) return;
    int start = rs[warp];
    int end = start + cnt[warp];
    float ax = 0.f, ay = 0.f, az = 0.f, aw = 0.f;
    int j = start;
    for (; j + 4 <= end; j += 4) {
        int s0 = esrc[j], s1 = esrc[j + 1], s2 = esrc[j + 2], s3 = esrc[j + 3];
        float w0 = ew[j], w1 = ew[j + 1], w2 = ew[j + 2], w3 = ew[j + 3];
        float4 v0 = *(const float4*)(t + (size_t)s0 * 128 + lane * 4);
        float4 v1 = *(const float4*)(t + (size_t)s1 * 128 + lane * 4);
        float4 v2 = *(const float4*)(t + (size_t)s2 * 128 + lane * 4);
        float4 v3 = *(const float4*)(t + (size_t)s3 * 128 + lane * 4);
        ax += w0 * v0.x; ay += w0 * v0.y; az += w0 * v0.z; aw += w0 * v0.w;
        ax += w1 * v1.x; ay += w1 * v1.y; az += w1 * v1.z; aw += w1 * v1.w;
        ax += w2 * v2.x; ay += w2 * v2.y; az += w2 * v2.z; aw += w2 * v2.w;
        ax += w3 * v3.x; ay += w3 * v3.y; az += w3 * v3.z; aw += w3 * v3.w;
    }
    for (; j < end; j++) {
        int s = esrc[j];
        float w = ew[j];
        float4 v = *(const float4*)(t + (size_t)s * 128 + lane * 4);
        ax += w * v.x; ay += w * v.y; az += w * v.z; aw += w * v.w;
    }
    *(float4*)(out + (size_t)warp * 128 + lane * 4) = make_float4(ax, ay, az, aw);
}

// ---------------- 3xFP16 (Markidis split) tensor-core GEMM ----------------
__device__ __forceinline__ void split_h(float f, __half& hi, __half& lo) {
    hi = __float2half_rn(f);
    lo = __float2half_rn(f - __half2float(hi));
}

__device__ __forceinline__ void mma_f16(float& d0, float& d1, float& d2, float& d3,
                                        unsigned a0, unsigned a1, unsigned a2, unsigned a3,
                                        unsigned b0, unsigned b1) {
    asm volatile(
        "mma.sync.aligned.m16n8k16.row.col.f32.f16.f16.f32 "
        "{%0,%1,%2,%3}, {%4,%5,%6,%7}, {%8,%9}, {%0,%1,%2,%3};"
        : "+f"(d0), "+f"(d1), "+f"(d2), "+f"(d3)
        : "r"(a0), "r"(a1), "r"(a2), "r"(a3), "r"(b0), "r"(b1));
}

// C[M,NOUT] = A[M,KTOT] @ W[KTOT,NOUT] + bias; EPI: 0=none 1=relu 2=elu
// CHEB: A cols 0..127 = A0, 128..255 = A1, 256..383 = 2*A2 - A0
template<int KTOT, int NOUT, int EPI, bool CHEB>
__global__ void __launch_bounds__(256)
gemm_f16x2(const float* __restrict__ A0, const float* __restrict__ A1,
           const float* __restrict__ A2, const float* __restrict__ W,
           const float* __restrict__ bias, float* __restrict__ C, int M) {
    constexpr int BM = 128, BK = 32, BN = NOUT;
    constexpr int KP = BK / 2;               // half2 k-pair rows (16)
    constexpr int WARP_N = BN / 2;
    constexpr int NT = WARP_N / 8;
    constexpr int ASTR = BM + 8;             // ≡ 8 mod 32 words: conflict-free frags
    constexpr int BSTR = BN + 8;

    __shared__ __half2 Ah[KP][ASTR], Al[KP][ASTR];
    __shared__ __half2 Bh[KP][BSTR], Bl[KP][BSTR];

    const int tid = threadIdx.x;
    const int w = tid >> 5, lane = tid & 31;
    const int wm = w & 3, wn = w >> 2;
    const int gid = lane >> 2, tig = lane & 3;
    const int row0 = blockIdx.x * BM;

    float acc[2][NT][4];
#pragma unroll
    for (int mt = 0; mt < 2; mt++)
#pragma unroll
        for (int nt = 0; nt < NT; nt++)
#pragma unroll
            for (int q = 0; q < 4; q++) acc[mt][nt][q] = 0.f;

    for (int k0 = 0; k0 < KTOT; k0 += BK) {
        // ---- stage A: thread holds float4 (4 consecutive k) for one m-row ----
#pragma unroll
        for (int it = 0; it < 4; it++) {
            int i = tid + it * 256;          // 0..1023
            int r = i & 127;
            int c4 = i >> 7;                 // 0..7
            int grow = row0 + r;
            int gk = k0 + c4 * 4;
            float4 v = make_float4(0.f, 0.f, 0.f, 0.f);
            if (grow < M) {
                if (CHEB) {
                    if (gk < 128) {
                        v = *(const float4*)(A0 + (size_t)grow * 128 + gk);
                    } else if (gk < 256) {
                        v = *(const float4*)(A1 + (size_t)grow * 128 + (gk - 128));
                    } else {
                        float4 p = *(const float4*)(A2 + (size_t)grow * 128 + (gk - 256));
                        float4 t = *(const float4*)(A0 + (size_t)grow * 128 + (gk - 256));
                        v = make_float4(2.f * p.x - t.x, 2.f * p.y - t.y,
                                        2.f * p.z - t.z, 2.f * p.w - t.w);
                    }
                } else {
                    v = *(const float4*)(A0 + (size_t)grow * KTOT + gk);
                }
            }
            __half hx, lx, hy, ly, hz, lz, hw, lw;
            split_h(v.x, hx, lx); split_h(v.y, hy, ly);
            split_h(v.z, hz, lz); split_h(v.w, hw, lw);
            Ah[c4 * 2 + 0][r] = __halves2half2(hx, hy);
            Ah[c4 * 2 + 1][r] = __halves2half2(hz, hw);
            Al[c4 * 2 + 0][r] = __halves2half2(lx, ly);
            Al[c4 * 2 + 1][r] = __halves2half2(lz, lw);
        }
        // ---- stage B: thread packs 2 k-rows x 4 n-cols ----
        constexpr int BSLOTS = KP * (BN / 4);
#pragma unroll
        for (int it = 0; it < (BSLOTS + 255) / 256; it++) {
            int i = tid + it * 256;
            if (BSLOTS % 256 != 0 && i >= BSLOTS) break;
            int kp = i / (BN / 4);
            int c = (i % (BN / 4)) * 4;
            float4 v0 = *(const float4*)(W + (size_t)(k0 + 2 * kp + 0) * BN + c);
            float4 v1 = *(const float4*)(W + (size_t)(k0 + 2 * kp + 1) * BN + c);
            float e0[4] = {v0.x, v0.y, v0.z, v0.w};
            float e1[4] = {v1.x, v1.y, v1.z, v1.w};
            __half2 hh[4], ll[4];
#pragma unroll
            for (int jq = 0; jq < 4; jq++) {
                __half h0, l0, h1, l1;
                split_h(e0[jq], h0, l0);
                split_h(e1[jq], h1, l1);
                hh[jq] = __halves2half2(h0, h1);
                ll[jq] = __halves2half2(l0, l1);
            }
            *(uint4*)&Bh[kp][c] = *(const uint4*)hh;
            *(uint4*)&Bl[kp][c] = *(const uint4*)ll;
        }
        __syncthreads();

#pragma unroll
        for (int ks = 0; ks < 2; ks++) {
            const int kb = ks * 8 + tig;
            unsigned ah[2][4], al[2][4];
#pragma unroll
            for (int mt = 0; mt < 2; mt++) {
                int m0 = wm * 32 + mt * 16 + gid;
                ah[mt][0] = *(const unsigned*)&Ah[kb][m0];
                ah[mt][1] = *(const unsigned*)&Ah[kb][m0 + 8];
                ah[mt][2] = *(const unsigned*)&Ah[kb + 4][m0];
                ah[mt][3] = *(const unsigned*)&Ah[kb + 4][m0 + 8];
                al[mt][0] = *(const unsigned*)&Al[kb][m0];
                al[mt][1] = *(const unsigned*)&Al[kb][m0 + 8];
                al[mt][2] = *(const unsigned*)&Al[kb + 4][m0];
                al[mt][3] = *(const unsigned*)&Al[kb + 4][m0 + 8];
            }
            unsigned bh[NT][2], bl[NT][2];
#pragma unroll
            for (int nt = 0; nt < NT; nt++) {
                int n0 = wn * WARP_N + nt * 8 + gid;
                bh[nt][0] = *(const unsigned*)&Bh[kb][n0];
                bh[nt][1] = *(const unsigned*)&Bh[kb + 4][n0];
                bl[nt][0] = *(const unsigned*)&Bl[kb][n0];
                bl[nt][1] = *(const unsigned*)&Bl[kb + 4][n0];
            }
#pragma unroll
            for (int mt = 0; mt < 2; mt++)
#pragma unroll
                for (int nt = 0; nt < NT; nt++) {
                    float* d = acc[mt][nt];
                    mma_f16(d[0], d[1], d[2], d[3],
                            ah[mt][0], ah[mt][1], ah[mt][2], ah[mt][3],
                            bh[nt][0], bh[nt][1]);
                    mma_f16(d[0], d[1], d[2], d[3],
                            ah[mt][0], ah[mt][1], ah[mt][2], ah[mt][3],
                            bl[nt][0], bl[nt][1]);
                    mma_f16(d[0], d[1], d[2], d[3],
                            al[mt][0], al[mt][1], al[mt][2], al[mt][3],
                            bh[nt][0], bh[nt][1]);
                }
        }
        __syncthreads();
    }

    // ---- epilogue ----
#pragma unroll
    for (int mt = 0; mt < 2; mt++) {
#pragma unroll
        for (int nt = 0; nt < NT; nt++) {
            int c0 = wn * WARP_N + nt * 8 + tig * 2;
            float bv0 = bias[c0], bv1 = bias[c0 + 1];
#pragma unroll
            for (int half = 0; half < 2; half++) {
                int r = row0 + wm * 32 + mt * 16 + gid + half * 8;
                if (r >= M) continue;
                float v0 = acc[mt][nt][half * 2 + 0] + bv0;
                float v1 = acc[mt][nt][half * 2 + 1] + bv1;
                if (EPI == 1) { v0 = fmaxf(v0, 0.f); v1 = fmaxf(v1, 0.f); }
                else if (EPI == 2) {
                    v0 = (v0 > 0.f) ? v0 : expm1f(v0);
                    v1 = (v1 > 0.f) ? v1 : expm1f(v1);
                }
                *(float2*)(C + (size_t)r * NOUT + c0) = make_float2(v0, v1);
            }
        }
    }
}

// ---------------- launch ----------------
extern "C" void kernel_launch(void* const* d_in, const int* in_sizes, int n_in,
                              void* d_out, int out_size) {
    const int* edge_index = (const int*)d_in[0];
    const int* node_attr = (const int*)d_in[1];
    const float* vis     = (const float*)d_in[2];
    const float* emb_len = (const float*)d_in[3];
    const float* emb_id  = (const float*)d_in[4];
    const float* emb_lng = (const float*)d_in[5];
    const float* emb_lat = (const float*)d_in[6];
    const float* W0  = (const float*)d_in[7];
    const float* b0  = (const float*)d_in[8];
    const float* W1  = (const float*)d_in[9];
    const float* b1  = (const float*)d_in[10];
    const float* P1  = (const float*)d_in[11];
    const float* pb1 = (const float*)d_in[12];
    const float* P2  = (const float*)d_in[13];
    const float* pb2 = (const float*)d_in[14];

    const int E = in_sizes[0] / 2;
    const int N = in_sizes[1] / 4;
    const int* src = edge_index;
    const int* dst = edge_index + E;

    float *x, *t1, *p, *h1, *tmp, *dinv, *ew;
    int *deg, *cnt, *rs, *rf, *bsum, *boff, *esrc;
    cudaGetSymbolAddress((void**)&x,    g_x);
    cudaGetSymbolAddress((void**)&t1,   g_t1);
    cudaGetSymbolAddress((void**)&p,    g_p);
    cudaGetSymbolAddress((void**)&h1,   g_h1);
    cudaGetSymbolAddress((void**)&tmp,  g_tmp);
    cudaGetSymbolAddress((void**)&dinv, g_dinv);
    cudaGetSymbolAddress((void**)&deg,  g_deg);
    cudaGetSymbolAddress((void**)&cnt,  g_cnt);
    cudaGetSymbolAddress((void**)&rs,   g_rs);
    cudaGetSymbolAddress((void**)&rf,   g_rf);
    cudaGetSymbolAddress((void**)&bsum, g_bsum);
    cudaGetSymbolAddress((void**)&boff, g_boff);
    cudaGetSymbolAddress((void**)&esrc, g_esrc);
    cudaGetSymbolAddress((void**)&ew,   g_ew);

    float* hout = (float*)d_out;
    float* zout = hout + (size_t)N * 128;

    const int nb = (N + 255) / 256;
    const int eb = (E + 255) / 256;
    const int gemm_blocks = (N + 127) / 128;
    const int prop_blocks = (N * 32 + 255) / 256;

    // CSR build + dinv (round-2 structure)
    cudaMemsetAsync(deg, 0, N * sizeof(int));
    cudaMemsetAsync(cnt, 0, N * sizeof(int));
    count_kernel<<<eb, 256>>>(src, dst, deg, cnt, E);
    dinv_kernel<<<nb, 256>>>(deg, dinv, N);
    scan_block_sum<<<nb, 256>>>(cnt, bsum, N);
    scan_top<<<1, 256>>>(bsum, boff, nb);
    scan_final<<<nb, 256>>>(cnt, boff, rs, rf, N);
    fill_kernel<<<eb, 256>>>(src, dst, dinv, rf, esrc, ew, E);

    // feature assembly
    build_x_kernel<<<(N * 32 + 255) / 256, 256>>>(node_attr, (const float4*)vis,
        (const float4*)emb_len, (const float4*)emb_id,
        (const float4*)emb_lng, (const float4*)emb_lat, (float4*)x, N);

    // ---- conv1 ----
    prop_gather<<<prop_blocks, 256>>>(x, rs, cnt, esrc, ew, t1, N);
    prop_gather<<<prop_blocks, 256>>>(t1, rs, cnt, esrc, ew, p, N);
    gemm_f16x2<384, 128, 1, true><<<gemm_blocks, 256>>>(x, t1, p, W0, b0, h1, N);

    // ---- conv2 ----
    prop_gather<<<prop_blocks, 256>>>(h1, rs, cnt, esrc, ew, t1, N);
    prop_gather<<<prop_blocks, 256>>>(t1, rs, cnt, esrc, ew, p, N);
    gemm_f16x2<384, 128, 1, true><<<gemm_blocks, 256>>>(h1, t1, p, W1, b1, hout, N);

    // ---- projection head ----
    gemm_f16x2<128, 128, 2, false><<<gemm_blocks, 256>>>(hout, nullptr, nullptr, P1, pb1, tmp, N);
    gemm_f16x2<128, 64, 0, false><<<gemm_blocks, 256>>>(tmp, nullptr, nullptr, P2, pb2, zout, N);
}